// round 1
// baseline (speedup 1.0000x reference)
#include <cuda_runtime.h>
#include <cstdint>

// OptFP_Embedding: out[b,f,:] = sum_i gm[g(x[b,f]), i] * fakequant(W[x[b,f],:], bits_i)
//
// Inputs (metadata order):
//   d_in[0] = x           int32   [4096*39]
//   d_in[1] = weight      float32 [1000000*64]
//   d_in[2] = group_index int32   [1000000]
//   d_in[3] = gamma       float32 [8*1*3]
//   d_in[4] = alpha       float32 [3]
//   d_in[5] = beta        float32 [64]
// Output: float32 [4096*39*64]

#define EMB_DIM 64
#define GROUPS 8
#define NBITS 3
#define THREADS_PER_TOKEN 16   // 16 threads x float4 = 64 floats
#define BLOCK_THREADS 256
#define TOKENS_PER_BLOCK (BLOCK_THREADS / THREADS_PER_TOKEN)

__global__ __launch_bounds__(BLOCK_THREADS)
void optfp_embedding_kernel(const int* __restrict__ x,
                            const float* __restrict__ weight,
                            const int* __restrict__ group_index,
                            const float* __restrict__ gamma,
                            const float* __restrict__ alpha,
                            const float* __restrict__ beta,
                            float* __restrict__ out,
                            int ntok) {
    __shared__ float s_beta[EMB_DIM];
    __shared__ float s_gm[GROUPS][NBITS];   // softmax(gamma/TAU) per group
    __shared__ float s_a[NBITS];            // |alpha| + eps
    __shared__ float s_inv_a[NBITS];

    const int tid = threadIdx.x;
    if (tid < EMB_DIM) s_beta[tid] = beta[tid];
    if (tid < NBITS) {
        float a = fabsf(alpha[tid]) + 1e-10f;
        s_a[tid] = a;
        s_inv_a[tid] = 1.0f / a;
    }
    if (tid < GROUPS) {
        // TAU = 1.0
        float g0 = gamma[tid * NBITS + 0];
        float g1 = gamma[tid * NBITS + 1];
        float g2 = gamma[tid * NBITS + 2];
        float m = fmaxf(g0, fmaxf(g1, g2));
        float e0 = __expf(g0 - m);
        float e1 = __expf(g1 - m);
        float e2 = __expf(g2 - m);
        float inv = 1.0f / (e0 + e1 + e2);
        s_gm[tid][0] = e0 * inv;
        s_gm[tid][1] = e1 * inv;
        s_gm[tid][2] = e2 * inv;
    }
    __syncthreads();

    const int token = blockIdx.x * TOKENS_PER_BLOCK + (tid >> 4);
    if (token >= ntok) return;
    const int lane = tid & (THREADS_PER_TOKEN - 1);

    const int idx = __ldg(x + token);
    const int g = __ldg(group_index + idx);

    const float gm0 = s_gm[g][0];
    const float gm1 = s_gm[g][1];
    const float gm2 = s_gm[g][2];
    const float a0 = s_a[0], a1 = s_a[1], a2 = s_a[2];
    const float ia0 = s_inv_a[0], ia1 = s_inv_a[1], ia2 = s_inv_a[2];

    const float4 w = __ldg((const float4*)(weight + (size_t)idx * EMB_DIM) + lane);
    const float4 b4 = ((const float4*)s_beta)[lane];

    float4 r;
    {
        const float wv[4] = {w.x, w.y, w.z, w.w};
        const float bv[4] = {b4.x, b4.y, b4.z, b4.w};
        float rv[4];
#pragma unroll
        for (int c = 0; c < 4; c++) {
            const float wb = wv[c] - bv[c];
            // bits=2: [-2, 1]
            float q0 = fminf(fmaxf(rintf(wb * ia0), -2.0f), 1.0f) * a0 + bv[c];
            // bits=4: [-8, 7]
            float q1 = fminf(fmaxf(rintf(wb * ia1), -8.0f), 7.0f) * a1 + bv[c];
            // bits=8: [-128, 127]
            float q2 = fminf(fmaxf(rintf(wb * ia2), -128.0f), 127.0f) * a2 + bv[c];
            rv[c] = gm0 * q0 + gm1 * q1 + gm2 * q2;
        }
        r.x = rv[0]; r.y = rv[1]; r.z = rv[2]; r.w = rv[3];
    }

    ((float4*)out)[(size_t)token * THREADS_PER_TOKEN + lane] = r;
}

extern "C" void kernel_launch(void* const* d_in, const int* in_sizes, int n_in,
                              void* d_out, int out_size) {
    const int*   x           = (const int*)d_in[0];
    const float* weight      = (const float*)d_in[1];
    const int*   group_index = (const int*)d_in[2];
    const float* gamma       = (const float*)d_in[3];
    const float* alpha       = (const float*)d_in[4];
    const float* beta        = (const float*)d_in[5];
    float* out = (float*)d_out;

    const int ntok = in_sizes[0];  // 4096 * 39 = 159744
    const int blocks = (ntok + TOKENS_PER_BLOCK - 1) / TOKENS_PER_BLOCK;
    optfp_embedding_kernel<<<blocks, BLOCK_THREADS>>>(
        x, weight, group_index, gamma, alpha, beta, out, ntok);
}

// round 2
// speedup vs baseline: 1.3774x; 1.3774x over previous
#include <cuda_runtime.h>
#include <cstdint>

// OptFP_Embedding: out[b,f,:] = beta + sum_i c_i(g) * clip(rint((W[x]-beta)*ia_i), lo_i, hi_i)
//   where c_i = softmax(gamma)_i * (|alpha_i|+eps), using  sum_i softmax = 1 to fold beta.
//
// Inputs (metadata order):
//   d_in[0] = x           int32   [4096*39]
//   d_in[1] = weight      float32 [1000000*64]
//   d_in[2] = group_index int32   [1000000]
//   d_in[3] = gamma       float32 [8*1*3]
//   d_in[4] = alpha       float32 [3]
//   d_in[5] = beta        float32 [64]
// Output: float32 [4096*39*64]

#define EMB_DIM 64
#define GROUPS 8
#define NBITS 3
#define TPT 16                 // threads per token (16 x float4 = 64 floats)
#define BLOCK_THREADS 256
#define TOK_PER_THREAD 4       // MLP: 4 independent row gathers in flight per thread
#define TOKENS_PER_BLOCK ((BLOCK_THREADS / TPT) * TOK_PER_THREAD)   // 64

__global__ __launch_bounds__(BLOCK_THREADS)
void optfp_embedding_kernel(const int* __restrict__ x,
                            const float* __restrict__ weight,
                            const int* __restrict__ group_index,
                            const float* __restrict__ gamma,
                            const float* __restrict__ alpha,
                            const float* __restrict__ beta,
                            float* __restrict__ out,
                            int ntok) {
    __shared__ float s_beta[EMB_DIM];
    __shared__ float s_c[GROUPS][NBITS];    // softmax(gamma)_i * a_i
    __shared__ float s_ia[NBITS];           // 1 / (|alpha_i| + eps)

    const int tid = threadIdx.x;
    if (tid < EMB_DIM) s_beta[tid] = beta[tid];
    if (tid < GROUPS) {
        // TAU = 1.0
        float g0 = gamma[tid * NBITS + 0];
        float g1 = gamma[tid * NBITS + 1];
        float g2 = gamma[tid * NBITS + 2];
        float m = fmaxf(g0, fmaxf(g1, g2));
        float e0 = __expf(g0 - m);
        float e1 = __expf(g1 - m);
        float e2 = __expf(g2 - m);
        float inv = 1.0f / (e0 + e1 + e2);
        float a0 = fabsf(alpha[0]) + 1e-10f;
        float a1 = fabsf(alpha[1]) + 1e-10f;
        float a2 = fabsf(alpha[2]) + 1e-10f;
        s_c[tid][0] = e0 * inv * a0;
        s_c[tid][1] = e1 * inv * a1;
        s_c[tid][2] = e2 * inv * a2;
        if (tid == 0) {
            s_ia[0] = 1.0f / a0;
            s_ia[1] = 1.0f / a1;
            s_ia[2] = 1.0f / a2;
        }
    }
    __syncthreads();

    const int sub  = tid >> 4;            // 0..15 : which token slot in block
    const int lane = tid & (TPT - 1);     // 0..15 : which float4 of the row

    const int base = blockIdx.x * TOKENS_PER_BLOCK + sub;

    // ---- Front-batched independent loads: 4 idx -> 4 group + 4 rows ----
    int tok[TOK_PER_THREAD];
    bool valid[TOK_PER_THREAD];
    int idx[TOK_PER_THREAD];
#pragma unroll
    for (int k = 0; k < TOK_PER_THREAD; k++) {
        tok[k]   = base + k * (BLOCK_THREADS / TPT);
        valid[k] = tok[k] < ntok;
        idx[k]   = valid[k] ? __ldg(x + tok[k]) : 0;
    }

    int g[TOK_PER_THREAD];
#pragma unroll
    for (int k = 0; k < TOK_PER_THREAD; k++)
        g[k] = __ldg(group_index + idx[k]);

    float4 w[TOK_PER_THREAD];
#pragma unroll
    for (int k = 0; k < TOK_PER_THREAD; k++)
        w[k] = __ldg((const float4*)(weight + (size_t)idx[k] * EMB_DIM) + lane);

    const float4 b4 = ((const float4*)s_beta)[lane];
    const float ia0 = s_ia[0], ia1 = s_ia[1], ia2 = s_ia[2];

#pragma unroll
    for (int k = 0; k < TOK_PER_THREAD; k++) {
        if (!valid[k]) continue;
        const float c0 = s_c[g[k]][0];
        const float c1 = s_c[g[k]][1];
        const float c2 = s_c[g[k]][2];

        const float wv[4] = {w[k].x, w[k].y, w[k].z, w[k].w};
        const float bv[4] = {b4.x, b4.y, b4.z, b4.w};
        float rv[4];
#pragma unroll
        for (int c = 0; c < 4; c++) {
            const float wb = wv[c] - bv[c];
            const float r0 = fminf(fmaxf(rintf(wb * ia0),   -2.0f),   1.0f);
            const float r1 = fminf(fmaxf(rintf(wb * ia1),   -8.0f),   7.0f);
            const float r2 = fminf(fmaxf(rintf(wb * ia2), -128.0f), 127.0f);
            rv[c] = bv[c] + c0 * r0 + c1 * r1 + c2 * r2;
        }
        float4 r; r.x = rv[0]; r.y = rv[1]; r.z = rv[2]; r.w = rv[3];
        __stcs((float4*)out + (size_t)tok[k] * TPT + lane, r);
    }
}

extern "C" void kernel_launch(void* const* d_in, const int* in_sizes, int n_in,
                              void* d_out, int out_size) {
    const int*   x           = (const int*)d_in[0];
    const float* weight      = (const float*)d_in[1];
    const int*   group_index = (const int*)d_in[2];
    const float* gamma       = (const float*)d_in[3];
    const float* alpha       = (const float*)d_in[4];
    const float* beta        = (const float*)d_in[5];
    float* out = (float*)d_out;

    const int ntok = in_sizes[0];  // 4096 * 39 = 159744
    const int blocks = (ntok + TOKENS_PER_BLOCK - 1) / TOKENS_PER_BLOCK;
    optfp_embedding_kernel<<<blocks, BLOCK_THREADS>>>(
        x, weight, group_index, gamma, alpha, beta, out, ntok);
}